// round 12
// baseline (speedup 1.0000x reference)
#include <cuda_runtime.h>
#include <math.h>
#include <stdint.h>

// Problem shape (fixed by reference setup_inputs)
#define BB 8
#define DD 64
#define HW (256 * 512)        // 131072
#define PIXELS (BB * HW)      // 1048576
#define TPB 128
#define PPT 8                 // pixels per thread
#define NBLOCKS (PIXELS / PPT / TPB)   // 1024
#define TILE (TPB * PPT)      // 1024 floats = 4096 B per block per d-slice

#define STAGES 8
#define DIST   7

#define LOG2E     1.4426950408889634f
#define INV_LOG2E 0.6931471805599453f
#define TWO_LOG2E 2.8853900817779268f
#define INV_1ME2  1.1565176427496657f   // 1/(1-e^-2)

// Allocation-free scratch
__device__ float        g_partial[NBLOCKS];
__device__ int          g_pcnt[NBLOCKS];
__device__ unsigned int g_done;

__device__ __forceinline__ float ex2(float x) {
    float r;
    asm("ex2.approx.f32 %0, %1;" : "=f"(r) : "f"(x));
    return r;
}
__device__ __forceinline__ float lg2(float x) {
    float r;
    asm("lg2.approx.f32 %0, %1;" : "=f"(r) : "f"(x));
    return r;
}
__device__ __forceinline__ void mbar_init(uint32_t addr, uint32_t count) {
    asm volatile("mbarrier.init.shared.b64 [%0], %1;" :: "r"(addr), "r"(count) : "memory");
}
__device__ __forceinline__ void mbar_expect_tx(uint32_t addr, uint32_t bytes) {
    asm volatile("mbarrier.arrive.expect_tx.shared.b64 _, [%0], %1;"
                 :: "r"(addr), "r"(bytes) : "memory");
}
__device__ __forceinline__ void bulk_g2s(uint32_t dst, const void* src,
                                         uint32_t bytes, uint32_t mbar) {
    asm volatile("cp.async.bulk.shared::cta.global.mbarrier::complete_tx::bytes "
                 "[%0], [%1], %2, [%3];"
                 :: "r"(dst), "l"(src), "r"(bytes), "r"(mbar) : "memory");
}
__device__ __forceinline__ void mbar_wait(uint32_t addr, uint32_t parity) {
    asm volatile(
        "{\n\t.reg .pred P;\n"
        "W%=:\n\t"
        "mbarrier.try_wait.parity.shared.b64 P, [%0], %1;\n\t"
        "@P bra D%=;\n\t"
        "bra W%=;\n"
        "D%=:\n\t}"
        :: "r"(addr), "r"(parity) : "memory");
}

// entropy = (lg2(se) - sptx/spt) / log2e
//   se   = sum_d 2^{x*log2e};  w = 2^{-|dl - gl|};  sptx = sum_d w * (x*log2e)
//   gl = gt*log2e (hoisted; inf -> w = 0 self-masking), dl = 2d*log2e (uniform)
// spt closed form (two geometric series), epilogue-only.
__global__ void __launch_bounds__(TPB)
sce_fused_kernel(const float* __restrict__ sim, const float* __restrict__ gt,
                 float* __restrict__ out) {
    __shared__ __align__(16) float buf[STAGES][TILE];   // 32 KB staging
    __shared__ __align__(8) unsigned long long mbar[STAGES];

    const int tid = blockIdx.x * TPB + threadIdx.x;
    const int p   = tid * PPT;
    const int p0  = blockIdx.x * TILE;          // block's first pixel
    const int b   = p0 / HW;
    const int rem = p0 - b * HW;

    const float* src0 = sim + (size_t)b * DD * HW + rem;   // advance by HW per d

    uint32_t mb[STAGES];
    #pragma unroll
    for (int s = 0; s < STAGES; ++s)
        mb[s] = (uint32_t)__cvta_generic_to_shared(&mbar[s]);
    const uint32_t bufsm = (uint32_t)__cvta_generic_to_shared(&buf[0][0]);

    if (threadIdx.x == 0) {
        #pragma unroll
        for (int s = 0; s < STAGES; ++s) mbar_init(mb[s], 1);
    }
    __syncthreads();

    // Prologue: producer fills stages 0..DIST-1
    if (threadIdx.x == 0) {
        #pragma unroll
        for (int d = 0; d < DIST; ++d) {
            mbar_expect_tx(mb[d], TILE * 4);
            bulk_g2s(bufsm + d * (TILE * 4), src0 + (size_t)d * HW, TILE * 4, mb[d]);
        }
    }

    // Per-pixel constants
    float gtv[PPT], gl[PPT], se[PPT], sptx[PPT];
    {
        const float4 g0 = *(const float4*)(gt + p);
        const float4 g1 = *(const float4*)(gt + p + 4);
        gtv[0]=g0.x; gtv[1]=g0.y; gtv[2]=g0.z; gtv[3]=g0.w;
        gtv[4]=g1.x; gtv[5]=g1.y; gtv[6]=g1.z; gtv[7]=g1.w;
    }
    #pragma unroll
    for (int j = 0; j < PPT; ++j) {
        gl[j]   = gtv[j] * LOG2E;
        se[j]   = 0.f;
        sptx[j] = 0.f;
    }

    float dl = 0.0f;   // 2d * log2e, uniform

    #pragma unroll 2
    for (int d = 0; d < DD; ++d) {
        const int st = d & (STAGES - 1);
        // All reads of buffer (d+DIST)&7 (done at iter d-1) complete before refill
        __syncthreads();
        if (threadIdx.x == 0) {
            const int dn = d + DIST;
            if (dn < DD) {
                const int sn = dn & (STAGES - 1);
                mbar_expect_tx(mb[sn], TILE * 4);
                bulk_g2s(bufsm + sn * (TILE * 4), src0 + (size_t)dn * HW,
                         TILE * 4, mb[sn]);
            }
        }
        mbar_wait(mb[st], (uint32_t)((d >> 3) & 1));

        const float4 x0 = *(const float4*)&buf[st][threadIdx.x * PPT];
        const float4 x1 = *(const float4*)&buf[st][threadIdx.x * PPT + 4];

        {
            float xl;
            xl = x0.x * LOG2E; se[0] += ex2(xl); sptx[0] += ex2(-fabsf(dl - gl[0])) * xl;
            xl = x0.y * LOG2E; se[1] += ex2(xl); sptx[1] += ex2(-fabsf(dl - gl[1])) * xl;
            xl = x0.z * LOG2E; se[2] += ex2(xl); sptx[2] += ex2(-fabsf(dl - gl[2])) * xl;
            xl = x0.w * LOG2E; se[3] += ex2(xl); sptx[3] += ex2(-fabsf(dl - gl[3])) * xl;
            xl = x1.x * LOG2E; se[4] += ex2(xl); sptx[4] += ex2(-fabsf(dl - gl[4])) * xl;
            xl = x1.y * LOG2E; se[5] += ex2(xl); sptx[5] += ex2(-fabsf(dl - gl[5])) * xl;
            xl = x1.z * LOG2E; se[6] += ex2(xl); sptx[6] += ex2(-fabsf(dl - gl[6])) * xl;
            xl = x1.w * LOG2E; se[7] += ex2(xl); sptx[7] += ex2(-fabsf(dl - gl[7])) * xl;
        }
        dl += TWO_LOG2E;
    }

    float local = 0.f;
    int   cnt   = 0;
    #pragma unroll
    for (int j = 0; j < PPT; ++j) {
        const float gv = gtv[j];
        if (isfinite(gv)) {
            const float m   = floorf(gv * 0.5f);
            const float a   = gv - 2.0f * m;
            const float spt = (__expf(-a) - __expf(-gv - 2.0f)
                             + __expf(a - 2.0f) - __expf(gv - 128.0f)) * INV_1ME2;
            local += (lg2(se[j]) - __fdividef(sptx[j], spt)) * INV_LOG2E;
            cnt   += 1;
        }
    }

    // Block reduce (4 warps)
    #pragma unroll
    for (int o = 16; o > 0; o >>= 1) {
        local += __shfl_down_sync(0xffffffffu, local, o);
        cnt   += __shfl_down_sync(0xffffffffu, cnt, o);
    }
    __shared__ float ssum[4];
    __shared__ int   scnt[4];
    __shared__ bool  isLast;
    const int lane = threadIdx.x & 31;
    const int wid  = threadIdx.x >> 5;
    if (lane == 0) { ssum[wid] = local; scnt[wid] = cnt; }
    __syncthreads();
    if (wid == 0) {
        local = (lane < 4) ? ssum[lane] : 0.f;
        cnt   = (lane < 4) ? scnt[lane] : 0;
        #pragma unroll
        for (int o = 2; o > 0; o >>= 1) {
            local += __shfl_down_sync(0xffffffffu, local, o);
            cnt   += __shfl_down_sync(0xffffffffu, cnt, o);
        }
        if (lane == 0) {
            g_partial[blockIdx.x] = local;
            g_pcnt[blockIdx.x]    = cnt;
            __threadfence();
            unsigned int prev = atomicAdd(&g_done, 1u);
            isLast = (prev == (unsigned int)(gridDim.x - 1));
        }
    }
    __syncthreads();

    // Last finished block reduces all partials
    if (isLast) {
        __threadfence();
        const volatile float* vp = g_partial;
        const volatile int*   vc = g_pcnt;
        float s = 0.f;
        int   c = 0;
        #pragma unroll
        for (int k = 0; k < NBLOCKS / TPB; ++k) {
            s += vp[threadIdx.x + k * TPB];
            c += vc[threadIdx.x + k * TPB];
        }
        #pragma unroll
        for (int o = 16; o > 0; o >>= 1) {
            s += __shfl_down_sync(0xffffffffu, s, o);
            c += __shfl_down_sync(0xffffffffu, c, o);
        }
        if (lane == 0) { ssum[wid] = s; scnt[wid] = c; }
        __syncthreads();
        if (wid == 0) {
            s = (lane < 4) ? ssum[lane] : 0.f;
            c = (lane < 4) ? scnt[lane] : 0;
            #pragma unroll
            for (int o = 2; o > 0; o >>= 1) {
                s += __shfl_down_sync(0xffffffffu, s, o);
                c += __shfl_down_sync(0xffffffffu, c, o);
            }
            if (lane == 0) {
                out[0] = s / (float)c;
                g_done = 0;
            }
        }
    }
}

extern "C" void kernel_launch(void* const* d_in, const int* in_sizes, int n_in,
                              void* d_out, int out_size) {
    const float* sim = (const float*)d_in[0];
    const float* gt  = (const float*)d_in[1];
    float* out       = (float*)d_out;

    sce_fused_kernel<<<NBLOCKS, TPB>>>(sim, gt, out);
}

// round 13
// speedup vs baseline: 1.3157x; 1.3157x over previous
#include <cuda_runtime.h>
#include <cuda_pipeline.h>
#include <math.h>

// Problem shape (fixed by reference setup_inputs)
#define BB 8
#define DD 64
#define HW (256 * 512)        // 131072
#define PIXELS (BB * HW)      // 1048576
#define TPB 128
#define PPT 8                 // pixels per thread
#define NBLOCKS (PIXELS / PPT / TPB)   // 1024

#define STAGES 8
#define DIST   7

#define LOG2E     1.4426950408889634f
#define INV_LOG2E 0.6931471805599453f
#define TWO_LOG2E 2.8853900817779268f
#define INV_1ME2  1.1565176427496657f   // 1/(1-e^-2)

// Allocation-free scratch
__device__ float        g_partial[NBLOCKS];
__device__ int          g_pcnt[NBLOCKS];
__device__ unsigned int g_done;

__device__ __forceinline__ float ex2(float x) {
    float r;
    asm("ex2.approx.f32 %0, %1;" : "=f"(r) : "f"(x));
    return r;
}
__device__ __forceinline__ float lg2(float x) {
    float r;
    asm("lg2.approx.f32 %0, %1;" : "=f"(r) : "f"(x));
    return r;
}

// entropy = (lg2(se) - sptx/spt) / log2e
//   se   = sum_d 2^{x*log2e};  w = 2^{-|dl - gl|};  sptx = sum_d w*(x*log2e)
//   gl = gt*log2e (hoisted; inf -> w = 0 self-masking), dl = 2d*log2e (uniform)
// spt closed form (two geometric series), epilogue-only.
__global__ void __launch_bounds__(TPB)
sce_fused_kernel(const float* __restrict__ sim, const float* __restrict__ gt,
                 float* __restrict__ out) {
    __shared__ __align__(16) float4 buf[STAGES][TPB * 2];   // 32 KB staging

    const int tid = blockIdx.x * TPB + threadIdx.x;
    const int p   = tid * PPT;
    const int b   = p / HW;
    const int rem = p - b * HW;

    const float4* simv = (const float4*)(sim + (size_t)b * DD * HW + rem);

    // Per-pixel constants
    float gtv[PPT], gl[PPT], se[PPT], sptx[PPT];
    {
        const float4 g0 = *(const float4*)(gt + p);
        const float4 g1 = *(const float4*)(gt + p + 4);
        gtv[0]=g0.x; gtv[1]=g0.y; gtv[2]=g0.z; gtv[3]=g0.w;
        gtv[4]=g1.x; gtv[5]=g1.y; gtv[6]=g1.z; gtv[7]=g1.w;
    }
    #pragma unroll
    for (int j = 0; j < PPT; ++j) {
        gl[j]   = gtv[j] * LOG2E;
        se[j]   = 0.f;
        sptx[j] = 0.f;
    }

    // Prologue: prefetch d = 0..DIST-1 (one commit group per stage)
    #pragma unroll
    for (int d = 0; d < DIST; ++d) {
        __pipeline_memcpy_async(&buf[d][threadIdx.x * 2 + 0],
                                &simv[(size_t)d * (HW / 4) + 0], 16);
        __pipeline_memcpy_async(&buf[d][threadIdx.x * 2 + 1],
                                &simv[(size_t)d * (HW / 4) + 1], 16);
        __pipeline_commit();
    }

    // Carried source pointer for prefetches (slice d+DIST)
    const float4* srcp = simv + (size_t)DIST * (HW / 4);

    float dl = 0.0f;   // 2d * log2e, uniform

    #pragma unroll 8
    for (int d = 0; d < DD; ++d) {
        __pipeline_wait_prior(DIST - 1);
        const int st = d & (STAGES - 1);          // compile-time under unroll 8
        const float4 x0 = buf[st][threadIdx.x * 2 + 0];
        const float4 x1 = buf[st][threadIdx.x * 2 + 1];

        if (d + DIST < DD) {
            const int sn = (d + DIST) & (STAGES - 1);   // compile-time
            __pipeline_memcpy_async(&buf[sn][threadIdx.x * 2 + 0], srcp + 0, 16);
            __pipeline_memcpy_async(&buf[sn][threadIdx.x * 2 + 1], srcp + 1, 16);
        }
        __pipeline_commit();
        srcp += HW / 4;

        float xl;
        xl = x0.x * LOG2E; se[0] += ex2(xl); sptx[0] += ex2(-fabsf(dl - gl[0])) * xl;
        xl = x0.y * LOG2E; se[1] += ex2(xl); sptx[1] += ex2(-fabsf(dl - gl[1])) * xl;
        xl = x0.z * LOG2E; se[2] += ex2(xl); sptx[2] += ex2(-fabsf(dl - gl[2])) * xl;
        xl = x0.w * LOG2E; se[3] += ex2(xl); sptx[3] += ex2(-fabsf(dl - gl[3])) * xl;
        xl = x1.x * LOG2E; se[4] += ex2(xl); sptx[4] += ex2(-fabsf(dl - gl[4])) * xl;
        xl = x1.y * LOG2E; se[5] += ex2(xl); sptx[5] += ex2(-fabsf(dl - gl[5])) * xl;
        xl = x1.z * LOG2E; se[6] += ex2(xl); sptx[6] += ex2(-fabsf(dl - gl[6])) * xl;
        xl = x1.w * LOG2E; se[7] += ex2(xl); sptx[7] += ex2(-fabsf(dl - gl[7])) * xl;

        dl += TWO_LOG2E;
    }

    float local = 0.f;
    int   cnt   = 0;
    #pragma unroll
    for (int j = 0; j < PPT; ++j) {
        const float gv = gtv[j];
        if (isfinite(gv)) {
            const float m   = floorf(gv * 0.5f);
            const float a   = gv - 2.0f * m;
            const float spt = (__expf(-a) - __expf(-gv - 2.0f)
                             + __expf(a - 2.0f) - __expf(gv - 128.0f)) * INV_1ME2;
            local += (lg2(se[j]) - __fdividef(sptx[j], spt)) * INV_LOG2E;
            cnt   += 1;
        }
    }

    // Block reduce (4 warps)
    #pragma unroll
    for (int o = 16; o > 0; o >>= 1) {
        local += __shfl_down_sync(0xffffffffu, local, o);
        cnt   += __shfl_down_sync(0xffffffffu, cnt, o);
    }
    __shared__ float ssum[4];
    __shared__ int   scnt[4];
    __shared__ bool  isLast;
    const int lane = threadIdx.x & 31;
    const int wid  = threadIdx.x >> 5;
    if (lane == 0) { ssum[wid] = local; scnt[wid] = cnt; }
    __syncthreads();
    if (wid == 0) {
        local = (lane < 4) ? ssum[lane] : 0.f;
        cnt   = (lane < 4) ? scnt[lane] : 0;
        #pragma unroll
        for (int o = 2; o > 0; o >>= 1) {
            local += __shfl_down_sync(0xffffffffu, local, o);
            cnt   += __shfl_down_sync(0xffffffffu, cnt, o);
        }
        if (lane == 0) {
            g_partial[blockIdx.x] = local;
            g_pcnt[blockIdx.x]    = cnt;
            __threadfence();
            unsigned int prev = atomicAdd(&g_done, 1u);
            isLast = (prev == (unsigned int)(gridDim.x - 1));
        }
    }
    __syncthreads();

    // Last finished block reduces all partials
    if (isLast) {
        __threadfence();
        const volatile float* vp = g_partial;
        const volatile int*   vc = g_pcnt;
        float s = 0.f;
        int   c = 0;
        #pragma unroll
        for (int k = 0; k < NBLOCKS / TPB; ++k) {
            s += vp[threadIdx.x + k * TPB];
            c += vc[threadIdx.x + k * TPB];
        }
        #pragma unroll
        for (int o = 16; o > 0; o >>= 1) {
            s += __shfl_down_sync(0xffffffffu, s, o);
            c += __shfl_down_sync(0xffffffffu, c, o);
        }
        if (lane == 0) { ssum[wid] = s; scnt[wid] = c; }
        __syncthreads();
        if (wid == 0) {
            s = (lane < 4) ? ssum[lane] : 0.f;
            c = (lane < 4) ? scnt[lane] : 0;
            #pragma unroll
            for (int o = 2; o > 0; o >>= 1) {
                s += __shfl_down_sync(0xffffffffu, s, o);
                c += __shfl_down_sync(0xffffffffu, c, o);
            }
            if (lane == 0) {
                out[0] = s / (float)c;
                g_done = 0;
            }
        }
    }
}

extern "C" void kernel_launch(void* const* d_in, const int* in_sizes, int n_in,
                              void* d_out, int out_size) {
    const float* sim = (const float*)d_in[0];
    const float* gt  = (const float*)d_in[1];
    float* out       = (float*)d_out;

    sce_fused_kernel<<<NBLOCKS, TPB>>>(sim, gt, out);
}

// round 14
// speedup vs baseline: 1.3581x; 1.0322x over previous
#include <cuda_runtime.h>
#include <cuda_pipeline.h>
#include <math.h>

// Problem shape (fixed by reference setup_inputs)
#define BB 8
#define DD 64
#define HW (256 * 512)        // 131072
#define PIXELS (BB * HW)      // 1048576
#define TPB 128
#define PPT 8                 // pixels per thread
#define NBLOCKS (PIXELS / PPT / TPB)   // 1024

#define STAGES 6              // 24 KB staging -> 7 blocks/SM -> single wave
#define DIST   5

#define LOG2E     1.4426950408889634f
#define INV_LOG2E 0.6931471805599453f
#define TWO_LOG2E 2.8853900817779268f
#define INV_1ME2  1.1565176427496657f   // 1/(1-e^-2)

// Allocation-free scratch
__device__ float        g_partial[NBLOCKS];
__device__ int          g_pcnt[NBLOCKS];
__device__ unsigned int g_done;

__device__ __forceinline__ float ex2(float x) {
    float r;
    asm("ex2.approx.f32 %0, %1;" : "=f"(r) : "f"(x));
    return r;
}
__device__ __forceinline__ float lg2(float x) {
    float r;
    asm("lg2.approx.f32 %0, %1;" : "=f"(r) : "f"(x));
    return r;
}

// entropy = (lg2(se) - sptx/spt) / log2e
//   se   = sum_d 2^{x*log2e};  w = 2^{-|dl - gl|};  sptx = sum_d w*(x*log2e)
//   gl = gt*log2e (hoisted; inf -> w = 0 self-masking), dl = 2d*log2e (uniform)
// spt closed form (two geometric series), epilogue-only; gv rebuilt from gl.
__global__ void __launch_bounds__(TPB, 7)
sce_fused_kernel(const float* __restrict__ sim, const float* __restrict__ gt,
                 float* __restrict__ out) {
    __shared__ __align__(16) float4 buf[STAGES][TPB * 2];   // 24 KB staging

    const int tid = blockIdx.x * TPB + threadIdx.x;
    const int p   = tid * PPT;
    const int b   = p / HW;
    const int rem = p - b * HW;

    const float4* simv = (const float4*)(sim + (size_t)b * DD * HW + rem);

    // Per-pixel constants (gtv NOT kept live; gl carries everything)
    float gl[PPT], se[PPT], sptx[PPT];
    {
        const float4 g0 = *(const float4*)(gt + p);
        const float4 g1 = *(const float4*)(gt + p + 4);
        gl[0]=g0.x*LOG2E; gl[1]=g0.y*LOG2E; gl[2]=g0.z*LOG2E; gl[3]=g0.w*LOG2E;
        gl[4]=g1.x*LOG2E; gl[5]=g1.y*LOG2E; gl[6]=g1.z*LOG2E; gl[7]=g1.w*LOG2E;
    }
    #pragma unroll
    for (int j = 0; j < PPT; ++j) { se[j] = 0.f; sptx[j] = 0.f; }

    // Prologue: prefetch d = 0..DIST-1 (one commit group per stage)
    const float4* srcp = simv;
    #pragma unroll
    for (int d = 0; d < DIST; ++d) {
        __pipeline_memcpy_async(&buf[d][threadIdx.x * 2 + 0], srcp + 0, 16);
        __pipeline_memcpy_async(&buf[d][threadIdx.x * 2 + 1], srcp + 1, 16);
        __pipeline_commit();
        srcp += HW / 4;
    }
    // srcp now points at slice DIST

    float dl = 0.0f;   // 2d * log2e, uniform
    int   st = 0;      // read stage (d mod STAGES)
    int   sn = DIST;   // write stage ((d+DIST) mod STAGES)

    #pragma unroll 2
    for (int d = 0; d < DD; ++d) {
        __pipeline_wait_prior(DIST - 1);
        const float4 x0 = buf[st][threadIdx.x * 2 + 0];
        const float4 x1 = buf[st][threadIdx.x * 2 + 1];

        if (d + DIST < DD) {
            __pipeline_memcpy_async(&buf[sn][threadIdx.x * 2 + 0], srcp + 0, 16);
            __pipeline_memcpy_async(&buf[sn][threadIdx.x * 2 + 1], srcp + 1, 16);
        }
        __pipeline_commit();
        srcp += HW / 4;

        float xl;
        xl = x0.x * LOG2E; se[0] += ex2(xl); sptx[0] += ex2(-fabsf(dl - gl[0])) * xl;
        xl = x0.y * LOG2E; se[1] += ex2(xl); sptx[1] += ex2(-fabsf(dl - gl[1])) * xl;
        xl = x0.z * LOG2E; se[2] += ex2(xl); sptx[2] += ex2(-fabsf(dl - gl[2])) * xl;
        xl = x0.w * LOG2E; se[3] += ex2(xl); sptx[3] += ex2(-fabsf(dl - gl[3])) * xl;
        xl = x1.x * LOG2E; se[4] += ex2(xl); sptx[4] += ex2(-fabsf(dl - gl[4])) * xl;
        xl = x1.y * LOG2E; se[5] += ex2(xl); sptx[5] += ex2(-fabsf(dl - gl[5])) * xl;
        xl = x1.z * LOG2E; se[6] += ex2(xl); sptx[6] += ex2(-fabsf(dl - gl[6])) * xl;
        xl = x1.w * LOG2E; se[7] += ex2(xl); sptx[7] += ex2(-fabsf(dl - gl[7])) * xl;

        dl += TWO_LOG2E;
        st = (st + 1 == STAGES) ? 0 : st + 1;
        sn = (sn + 1 == STAGES) ? 0 : sn + 1;
    }

    float local = 0.f;
    int   cnt   = 0;
    #pragma unroll
    for (int j = 0; j < PPT; ++j) {
        if (isfinite(gl[j])) {
            const float gv  = gl[j] * INV_LOG2E;   // reconstruct gt
            const float m   = floorf(gv * 0.5f);
            const float a   = gv - 2.0f * m;
            const float spt = (__expf(-a) - __expf(-gv - 2.0f)
                             + __expf(a - 2.0f) - __expf(gv - 128.0f)) * INV_1ME2;
            local += (lg2(se[j]) - __fdividef(sptx[j], spt)) * INV_LOG2E;
            cnt   += 1;
        }
    }

    // Block reduce (4 warps)
    #pragma unroll
    for (int o = 16; o > 0; o >>= 1) {
        local += __shfl_down_sync(0xffffffffu, local, o);
        cnt   += __shfl_down_sync(0xffffffffu, cnt, o);
    }
    __shared__ float ssum[4];
    __shared__ int   scnt[4];
    __shared__ bool  isLast;
    const int lane = threadIdx.x & 31;
    const int wid  = threadIdx.x >> 5;
    if (lane == 0) { ssum[wid] = local; scnt[wid] = cnt; }
    __syncthreads();
    if (wid == 0) {
        local = (lane < 4) ? ssum[lane] : 0.f;
        cnt   = (lane < 4) ? scnt[lane] : 0;
        #pragma unroll
        for (int o = 2; o > 0; o >>= 1) {
            local += __shfl_down_sync(0xffffffffu, local, o);
            cnt   += __shfl_down_sync(0xffffffffu, cnt, o);
        }
        if (lane == 0) {
            g_partial[blockIdx.x] = local;
            g_pcnt[blockIdx.x]    = cnt;
            __threadfence();
            unsigned int prev = atomicAdd(&g_done, 1u);
            isLast = (prev == (unsigned int)(gridDim.x - 1));
        }
    }
    __syncthreads();

    // Last finished block reduces all partials
    if (isLast) {
        __threadfence();
        const volatile float* vp = g_partial;
        const volatile int*   vc = g_pcnt;
        float s = 0.f;
        int   c = 0;
        #pragma unroll
        for (int k = 0; k < NBLOCKS / TPB; ++k) {
            s += vp[threadIdx.x + k * TPB];
            c += vc[threadIdx.x + k * TPB];
        }
        #pragma unroll
        for (int o = 16; o > 0; o >>= 1) {
            s += __shfl_down_sync(0xffffffffu, s, o);
            c += __shfl_down_sync(0xffffffffu, c, o);
        }
        if (lane == 0) { ssum[wid] = s; scnt[wid] = c; }
        __syncthreads();
        if (wid == 0) {
            s = (lane < 4) ? ssum[lane] : 0.f;
            c = (lane < 4) ? scnt[lane] : 0;
            #pragma unroll
            for (int o = 2; o > 0; o >>= 1) {
                s += __shfl_down_sync(0xffffffffu, s, o);
                c += __shfl_down_sync(0xffffffffu, c, o);
            }
            if (lane == 0) {
                out[0] = s / (float)c;
                g_done = 0;
            }
        }
    }
}

extern "C" void kernel_launch(void* const* d_in, const int* in_sizes, int n_in,
                              void* d_out, int out_size) {
    const float* sim = (const float*)d_in[0];
    const float* gt  = (const float*)d_in[1];
    float* out       = (float*)d_out;

    sce_fused_kernel<<<NBLOCKS, TPB>>>(sim, gt, out);
}